// round 2
// baseline (speedup 1.0000x reference)
#include <cuda_runtime.h>
#include <cstdint>

#define BB 32
#define NN 65536
#define MM 64
#define TPB 256
#define BLOCKS_PER_IMG (NN / TPB)   // 256
#define EPSV 1e-6f

// Scratch (static __device__ globals: no allocation at runtime)
__device__ unsigned long long g_gt_best[BB * MM];          // packed (iou_bits<<32)|(~pred_idx)
__device__ float2             g_pred_best[BB * NN];        // (best_iou, bestj as int bits)  16MB
__device__ float4             g_partials[BB * BLOCKS_PER_IMG];

// ---------------------------------------------------------------------------
__global__ void k_init() {
    int t = blockIdx.x * blockDim.x + threadIdx.x;
    if (t < BB * MM) g_gt_best[t] = 0ull;
}

// ---------------------------------------------------------------------------
// Kernel A: per-pred best-GT argmax (registers) + per-GT best-pred argmax
// (REDUX + ballot + block staging + atomicMax on packed u64).
__global__ void __launch_bounds__(TPB) k_pairwise(const float* __restrict__ pred,
                                                  const float* __restrict__ gt) {
    const int b     = blockIdx.x / BLOCKS_PER_IMG;
    const int chunk = blockIdx.x % BLOCKS_PER_IMG;
    const int i     = chunk * TPB + threadIdx.x;          // per-image pred index

    __shared__ float sg0[MM], sg1[MM], sg2[MM], sg3[MM], sga[MM];
    __shared__ unsigned long long sred[MM][TPB / 32];     // per-warp winners

    if (threadIdx.x < MM) {
        const float* g = gt + ((size_t)b * MM + threadIdx.x) * 4;
        float x1 = g[0], y1 = g[1], x2 = g[2], y2 = g[3];
        sg0[threadIdx.x] = x1; sg1[threadIdx.x] = y1;
        sg2[threadIdx.x] = x2; sg3[threadIdx.x] = y2;
        sga[threadIdx.x] = (x2 - x1) * (y2 - y1);
    }
    __syncthreads();

    const float* p = pred + ((size_t)b * NN + i) * 5;
    float cx = p[0], cy = p[1], w = p[2], h = p[3];
    float px1 = cx - 0.5f * w, py1 = cy - 0.5f * h;
    float px2 = cx + 0.5f * w, py2 = cy + 0.5f * h;
    float area_p = (px2 - px1) * (py2 - py1);

    float bestv = -1.0f;
    int   bestj = 0;
    const int lane = threadIdx.x & 31;
    const int warp = threadIdx.x >> 5;

    #pragma unroll 4
    for (int j = 0; j < MM; j++) {
        float ix1 = fmaxf(px1, sg0[j]);
        float iy1 = fmaxf(py1, sg1[j]);
        float ix2 = fminf(px2, sg2[j]);
        float iy2 = fminf(py2, sg3[j]);
        float iw  = fmaxf(ix2 - ix1, 0.0f);
        float ih  = fmaxf(iy2 - iy1, 0.0f);
        float inter = iw * ih;
        float uni   = area_p + sga[j] - inter;
        float iou   = inter / fmaxf(uni, EPSV);           // precise div (match jnp)

        if (iou > bestv) { bestv = iou; bestj = j; }      // ascending j -> first max

        // per-GT warp argmax: value via REDUX, leader lane via ballot (lowest idx)
        unsigned int ib = __float_as_uint(iou);           // iou >= 0: bits monotone
        unsigned int mv = __reduce_max_sync(0xffffffffu, ib);
        unsigned int bl = __ballot_sync(0xffffffffu, ib == mv);
        if (lane == 0) {
            int leader = __ffs(bl) - 1;
            unsigned int li = (unsigned int)(chunk * TPB + warp * 32 + leader);
            sred[j][warp] = ((unsigned long long)mv << 32) | (0xFFFFFFFFu - li);
        }
    }

    g_pred_best[(size_t)b * NN + i] = make_float2(bestv, __int_as_float(bestj));

    __syncthreads();
    if (threadIdx.x < MM) {
        unsigned long long m = sred[threadIdx.x][0];
        #pragma unroll
        for (int wgi = 1; wgi < TPB / 32; wgi++) {
            unsigned long long v = sred[threadIdx.x][wgi];
            if (v > m) m = v;
        }
        atomicMax(&g_gt_best[b * MM + threadIdx.x], m);
    }
}

// ---------------------------------------------------------------------------
__device__ __forceinline__ float warp_sum(float v) {
    #pragma unroll
    for (int o = 16; o > 0; o >>= 1) v += __shfl_down_sync(0xffffffffu, v, o);
    return v;
}

// Kernel B: pos/neg assignment, focal + GIoU, block partial sums.
__global__ void __launch_bounds__(TPB) k_loss(const float* __restrict__ pred,
                                              const float* __restrict__ gt) {
    const int b = blockIdx.x / BLOCKS_PER_IMG;
    const int i = (blockIdx.x % BLOCKS_PER_IMG) * TPB + threadIdx.x;

    __shared__ float4 sgt[MM];
    __shared__ unsigned int sscat[MM];
    __shared__ float4 sredu[TPB / 32];

    if (threadIdx.x < MM) {
        sgt[threadIdx.x] = ((const float4*)gt)[(size_t)b * MM + threadIdx.x];
        unsigned long long pk = g_gt_best[b * MM + threadIdx.x];
        float v = __uint_as_float((unsigned int)(pk >> 32));
        unsigned int idx = 0xFFFFFFFFu - (unsigned int)(pk & 0xFFFFFFFFull);
        sscat[threadIdx.x] = (v > 0.1f) ? idx : 0xFFFFFFFFu;
    }
    __syncthreads();

    const float* p = pred + ((size_t)b * NN + i) * 5;
    float cx = p[0], cy = p[1], w = p[2], h = p[3], obj = p[4];
    float px1 = cx - 0.5f * w, py1 = cy - 0.5f * h;
    float px2 = cx + 0.5f * w, py2 = cy + 0.5f * h;
    float area_p = (px2 - px1) * (py2 - py1);

    float2 pb2 = g_pred_best[(size_t)b * NN + i];
    float bestv = pb2.x;
    int   bestj = __float_as_int(pb2.y);

    bool scat = false;
    #pragma unroll 8
    for (int j = 0; j < MM; j++) scat |= (sscat[j] == (unsigned int)i);

    bool pos   = scat || (bestv > 0.5f);
    bool neg   = bestv < 0.4f;
    bool valid = pos || neg;

    // focal
    float l   = obj;
    float t   = pos ? 1.0f : 0.0f;
    float bce = fmaxf(l, 0.0f) - l * t + log1pf(expf(-fabsf(l)));
    float pr  = 1.0f / (1.0f + expf(-l));
    float p_t = pos ? pr : 1.0f - pr;
    float a_t = pos ? 0.25f : 0.75f;
    float om  = 1.0f - p_t;
    float fl  = a_t * om * om * bce;

    // giou vs matched gt
    float4 g = sgt[bestj];
    float x1 = fmaxf(px1, g.x), y1 = fmaxf(py1, g.y);
    float x2 = fminf(px2, g.z), y2 = fminf(py2, g.w);
    float inter = fmaxf(x2 - x1, 0.0f) * fmaxf(y2 - y1, 0.0f);
    float ag  = (g.z - g.x) * (g.w - g.y);
    float uni = area_p + ag - inter;
    float iou = inter / fmaxf(uni, EPSV);
    float ex1 = fminf(px1, g.x), ey1 = fminf(py1, g.y);
    float ex2 = fmaxf(px2, g.z), ey2 = fmaxf(py2, g.w);
    float enc = (ex2 - ex1) * (ey2 - ey1);
    float giou = iou - (enc - uni) / fmaxf(enc, EPSV);
    float gterm = 1.0f - giou;

    float s0 = valid ? fl : 0.0f;
    float s1 = valid ? 1.0f : 0.0f;
    float s2 = pos ? gterm : 0.0f;
    float s3 = pos ? 1.0f : 0.0f;

    s0 = warp_sum(s0); s1 = warp_sum(s1); s2 = warp_sum(s2); s3 = warp_sum(s3);
    int lane = threadIdx.x & 31, warp = threadIdx.x >> 5;
    if (lane == 0) sredu[warp] = make_float4(s0, s1, s2, s3);
    __syncthreads();
    if (threadIdx.x < (TPB / 32)) {
        float4 v = sredu[threadIdx.x];
        #pragma unroll
        for (int o = (TPB / 64); o > 0; o >>= 1) {
            v.x += __shfl_down_sync(0xffu, v.x, o);
            v.y += __shfl_down_sync(0xffu, v.y, o);
            v.z += __shfl_down_sync(0xffu, v.z, o);
            v.w += __shfl_down_sync(0xffu, v.w, o);
        }
        if (threadIdx.x == 0) g_partials[blockIdx.x] = v;
    }
}

// ---------------------------------------------------------------------------
__global__ void __launch_bounds__(TPB) k_final(float* __restrict__ out) {
    __shared__ float s[TPB / 32];
    float cls_t = 0.0f, reg_t = 0.0f, npos_t = 0.0f;
    const int lane = threadIdx.x & 31, warp = threadIdx.x >> 5;

    for (int b = 0; b < BB; b++) {
        float4 v = g_partials[b * BLOCKS_PER_IMG + threadIdx.x];
        // reduce each component over the 256 threads
        float acc[4] = {v.x, v.y, v.z, v.w};
        float tot[4];
        #pragma unroll
        for (int c = 0; c < 4; c++) {
            float x = warp_sum(acc[c]);
            __syncthreads();
            if (lane == 0) s[warp] = x;
            __syncthreads();
            float r = 0.0f;
            if (threadIdx.x == 0) {
                #pragma unroll
                for (int k = 0; k < TPB / 32; k++) r += s[k];
            }
            tot[c] = r;
        }
        if (threadIdx.x == 0) {
            float fls = tot[0], vc = tot[1], gts = tot[2], pc = tot[3];
            float cls = (vc > 0.0f) ? fls / fmaxf(vc, 1.0f) : 0.0f;
            float reg = (pc > 0.0f) ? gts / fmaxf(pc, 1.0f) : 0.0f;
            cls_t += cls; reg_t += reg; npos_t += pc;
        }
    }
    if (threadIdx.x == 0) {
        float num_pos = fmaxf(npos_t, 1.0f);
        float total_cls = cls_t / (float)BB;
        float total_reg = reg_t / num_pos * (float)BB;
        out[0] = total_cls + 2.0f * total_reg;
    }
}

// ---------------------------------------------------------------------------
extern "C" void kernel_launch(void* const* d_in, const int* in_sizes, int n_in,
                              void* d_out, int out_size) {
    const float* pred = (const float*)d_in[0];
    const float* gt   = (const float*)d_in[1];
    // defensive: detect swapped input order by element counts
    if (n_in >= 2 && in_sizes[0] == BB * MM * 4 && in_sizes[1] == BB * NN * 5) {
        pred = (const float*)d_in[1];
        gt   = (const float*)d_in[0];
    }
    float* out = (float*)d_out;

    k_init<<<(BB * MM + 255) / 256, 256>>>();
    k_pairwise<<<BB * BLOCKS_PER_IMG, TPB>>>(pred, gt);
    k_loss<<<BB * BLOCKS_PER_IMG, TPB>>>(pred, gt);
    k_final<<<1, TPB>>>(out);
}

// round 4
// speedup vs baseline: 2.0910x; 2.0910x over previous
#include <cuda_runtime.h>
#include <cstdint>

#define BB 32
#define NN 65536
#define MM 64
#define TPB 256
#define BLOCKS_PER_IMG (NN / TPB)   // 256
#define EPSV 1e-6f

// Scratch (static __device__ globals: no runtime allocation)
__device__ unsigned long long g_gt_best[BB * MM];       // packed (iou_bits<<32)|(~pred_idx)
__device__ float2             g_pred_best[BB * NN];     // (best_iou, bestj bits)
__device__ float4             g_partials[BB * BLOCKS_PER_IMG];
__device__ float4             g_img[BB];                // per-image (cls, reg, npos, -)

// ---------------------------------------------------------------------------
__global__ void k_init() {
    int t = blockIdx.x * blockDim.x + threadIdx.x;
    if (t < BB * MM) g_gt_best[t] = 0ull;
}

// ---------------------------------------------------------------------------
// Kernel A: per-pred best-GT argmax (registers) + per-GT best-pred argmax
// (REDUX + ballot + block staging + atomicMax on packed u64).
__global__ void __launch_bounds__(TPB) k_pairwise(const float* __restrict__ pred,
                                                  const float* __restrict__ gt) {
    const int b     = blockIdx.x / BLOCKS_PER_IMG;
    const int chunk = blockIdx.x % BLOCKS_PER_IMG;
    const int i     = chunk * TPB + threadIdx.x;          // per-image pred index

    __shared__ float4 sgt[MM];
    __shared__ float  sga[MM];
    __shared__ unsigned long long sred[MM][TPB / 32];     // per-warp winners

    if (threadIdx.x < MM) {
        float4 g4 = ((const float4*)gt)[(size_t)b * MM + threadIdx.x];
        sgt[threadIdx.x] = g4;
        sga[threadIdx.x] = (g4.z - g4.x) * (g4.w - g4.y);
    }
    __syncthreads();

    const float* p = pred + ((size_t)b * NN + i) * 5;
    float cx = p[0], cy = p[1], w = p[2], h = p[3];
    float px1 = cx - 0.5f * w, py1 = cy - 0.5f * h;
    float px2 = cx + 0.5f * w, py2 = cy + 0.5f * h;
    float area_p = (px2 - px1) * (py2 - py1);

    float bestv = -1.0f;
    int   bestj = 0;
    const int lane = threadIdx.x & 31;
    const int warp = threadIdx.x >> 5;

    #pragma unroll 8
    for (int j = 0; j < MM; j++) {
        float4 g = sgt[j];
        float ix1 = fmaxf(px1, g.x);
        float iy1 = fmaxf(py1, g.y);
        float ix2 = fminf(px2, g.z);
        float iy2 = fminf(py2, g.w);
        float iw  = fmaxf(ix2 - ix1, 0.0f);
        float ih  = fmaxf(iy2 - iy1, 0.0f);
        float inter = iw * ih;
        float uni   = area_p + sga[j] - inter;
        float iou   = __fdividef(inter, fmaxf(uni, EPSV));   // fast div (MUFU.RCP)

        if (iou > bestv) { bestv = iou; bestj = j; }      // ascending j -> first max

        // per-GT warp argmax: value via REDUX, leader lane via ballot (lowest idx)
        unsigned int ib = __float_as_uint(iou);           // iou >= 0: bits monotone
        unsigned int mv = __reduce_max_sync(0xffffffffu, ib);
        unsigned int bl = __ballot_sync(0xffffffffu, ib == mv);
        if (lane == 0) {
            int leader = __ffs(bl) - 1;
            unsigned int li = (unsigned int)(chunk * TPB + warp * 32 + leader);
            sred[j][warp] = ((unsigned long long)mv << 32) | (0xFFFFFFFFu - li);
        }
    }

    g_pred_best[(size_t)b * NN + i] = make_float2(bestv, __int_as_float(bestj));

    __syncthreads();
    if (threadIdx.x < MM) {
        unsigned long long m = sred[threadIdx.x][0];
        #pragma unroll
        for (int wgi = 1; wgi < TPB / 32; wgi++) {
            unsigned long long v = sred[threadIdx.x][wgi];
            if (v > m) m = v;
        }
        atomicMax(&g_gt_best[b * MM + threadIdx.x], m);
    }
}

// ---------------------------------------------------------------------------
__device__ __forceinline__ float warp_sum(float v) {
    #pragma unroll
    for (int o = 16; o > 0; o >>= 1) v += __shfl_down_sync(0xffffffffu, v, o);
    return v;
}

// Kernel B: pos/neg assignment, focal + GIoU, block partial sums.
__global__ void __launch_bounds__(TPB) k_loss(const float* __restrict__ pred,
                                              const float* __restrict__ gt) {
    const int b = blockIdx.x / BLOCKS_PER_IMG;
    const int i = (blockIdx.x % BLOCKS_PER_IMG) * TPB + threadIdx.x;

    __shared__ float4 sgt[MM];
    __shared__ unsigned int sscat[MM];
    __shared__ float4 sredu[TPB / 32];

    if (threadIdx.x < MM) {
        sgt[threadIdx.x] = ((const float4*)gt)[(size_t)b * MM + threadIdx.x];
        unsigned long long pk = g_gt_best[b * MM + threadIdx.x];
        float v = __uint_as_float((unsigned int)(pk >> 32));
        unsigned int idx = 0xFFFFFFFFu - (unsigned int)(pk & 0xFFFFFFFFull);
        sscat[threadIdx.x] = (v > 0.1f) ? idx : 0xFFFFFFFFu;
    }
    __syncthreads();

    const float* p = pred + ((size_t)b * NN + i) * 5;
    float cx = p[0], cy = p[1], w = p[2], h = p[3], obj = p[4];
    float px1 = cx - 0.5f * w, py1 = cy - 0.5f * h;
    float px2 = cx + 0.5f * w, py2 = cy + 0.5f * h;
    float area_p = (px2 - px1) * (py2 - py1);

    float2 pb2 = g_pred_best[(size_t)b * NN + i];
    float bestv = pb2.x;
    int   bestj = __float_as_int(pb2.y);

    bool scat = false;
    #pragma unroll 8
    for (int j = 0; j < MM; j++) scat |= (sscat[j] == (unsigned int)i);

    bool pos   = scat || (bestv > 0.5f);
    bool neg   = bestv < 0.4f;
    bool valid = pos || neg;

    // focal
    float l   = obj;
    float t   = pos ? 1.0f : 0.0f;
    float bce = fmaxf(l, 0.0f) - l * t + log1pf(expf(-fabsf(l)));
    float pr  = 1.0f / (1.0f + expf(-l));
    float p_t = pos ? pr : 1.0f - pr;
    float a_t = pos ? 0.25f : 0.75f;
    float om  = 1.0f - p_t;
    float fl  = a_t * om * om * bce;

    // giou vs matched gt
    float4 g = sgt[bestj];
    float x1 = fmaxf(px1, g.x), y1 = fmaxf(py1, g.y);
    float x2 = fminf(px2, g.z), y2 = fminf(py2, g.w);
    float inter = fmaxf(x2 - x1, 0.0f) * fmaxf(y2 - y1, 0.0f);
    float ag  = (g.z - g.x) * (g.w - g.y);
    float uni = area_p + ag - inter;
    float iou = __fdividef(inter, fmaxf(uni, EPSV));
    float ex1 = fminf(px1, g.x), ey1 = fminf(py1, g.y);
    float ex2 = fmaxf(px2, g.z), ey2 = fmaxf(py2, g.w);
    float enc = (ex2 - ex1) * (ey2 - ey1);
    float giou = iou - __fdividef(enc - uni, fmaxf(enc, EPSV));
    float gterm = 1.0f - giou;

    float s0 = valid ? fl : 0.0f;
    float s1 = valid ? 1.0f : 0.0f;
    float s2 = pos ? gterm : 0.0f;
    float s3 = pos ? 1.0f : 0.0f;

    s0 = warp_sum(s0); s1 = warp_sum(s1); s2 = warp_sum(s2); s3 = warp_sum(s3);
    int lane = threadIdx.x & 31, warp = threadIdx.x >> 5;
    if (lane == 0) sredu[warp] = make_float4(s0, s1, s2, s3);
    __syncthreads();
    if (threadIdx.x < (TPB / 32)) {
        float4 v = sredu[threadIdx.x];
        #pragma unroll
        for (int o = (TPB / 64); o > 0; o >>= 1) {
            v.x += __shfl_down_sync(0xffu, v.x, o);
            v.y += __shfl_down_sync(0xffu, v.y, o);
            v.z += __shfl_down_sync(0xffu, v.z, o);
            v.w += __shfl_down_sync(0xffu, v.w, o);
        }
        if (threadIdx.x == 0) g_partials[blockIdx.x] = v;
    }
}

// ---------------------------------------------------------------------------
// Per-image reduction: one block per image, 256 partials each.
__global__ void __launch_bounds__(TPB) k_reduce_img() {
    const int b = blockIdx.x;
    __shared__ float4 s[TPB / 32];

    float4 v = g_partials[b * BLOCKS_PER_IMG + threadIdx.x];
    v.x = warp_sum(v.x); v.y = warp_sum(v.y);
    v.z = warp_sum(v.z); v.w = warp_sum(v.w);
    int lane = threadIdx.x & 31, warp = threadIdx.x >> 5;
    if (lane == 0) s[warp] = v;
    __syncthreads();
    if (threadIdx.x == 0) {
        float fls = 0.f, vc = 0.f, gts = 0.f, pc = 0.f;
        #pragma unroll
        for (int k = 0; k < TPB / 32; k++) {
            fls += s[k].x; vc += s[k].y; gts += s[k].z; pc += s[k].w;
        }
        float cls = (vc > 0.0f) ? fls / fmaxf(vc, 1.0f) : 0.0f;
        float reg = (pc > 0.0f) ? gts / fmaxf(pc, 1.0f) : 0.0f;
        g_img[b] = make_float4(cls, reg, pc, 0.0f);
    }
}

// Final combine: one warp over 32 images.
__global__ void k_final2(float* __restrict__ out) {
    float4 v = g_img[threadIdx.x];
    float cls = warp_sum(v.x);
    float reg = warp_sum(v.y);
    float pc  = warp_sum(v.z);
    if (threadIdx.x == 0) {
        float num_pos = fmaxf(pc, 1.0f);
        out[0] = cls / (float)BB + 2.0f * (reg / num_pos * (float)BB);
    }
}

// ---------------------------------------------------------------------------
extern "C" void kernel_launch(void* const* d_in, const int* in_sizes, int n_in,
                              void* d_out, int out_size) {
    const float* pred = (const float*)d_in[0];
    const float* gt   = (const float*)d_in[1];
    if (n_in >= 2 && in_sizes[0] == BB * MM * 4 && in_sizes[1] == BB * NN * 5) {
        pred = (const float*)d_in[1];
        gt   = (const float*)d_in[0];
    }
    float* out = (float*)d_out;

    k_init<<<(BB * MM + 255) / 256, 256>>>();
    k_pairwise<<<BB * BLOCKS_PER_IMG, TPB>>>(pred, gt);
    k_loss<<<BB * BLOCKS_PER_IMG, TPB>>>(pred, gt);
    k_reduce_img<<<BB, TPB>>>();
    k_final2<<<1, 32>>>(out);
}